// round 1
// baseline (speedup 1.0000x reference)
#include <cuda_runtime.h>
#include <math.h>

#define N_NODES 100000
#define N_EDGES 1600000
#define CAP 96   // max in-degree kept per node; Poisson(16) tail beyond 96 is ~1e-40

// ---------------- static device scratch (no allocations allowed) ----------------
__device__ float g_y[(size_t)N_NODES * 128];   // post-GEMM features (pre-aggregation)
__device__ float g_h[(size_t)N_NODES * 128];   // post-layer features
__device__ int   g_csr[(size_t)N_NODES * CAP]; // incoming src lists, bucketed by dst
__device__ int   g_cnt[N_NODES];               // in-degree (also CSR fill counter)
__device__ int   g_outdeg[N_NODES];            // out-degree
__device__ float g_nsrc[N_NODES];              // out_deg^-1/2 (clipped)
__device__ float g_ndst[N_NODES];              // in_deg^-1/2 (clipped)

// ---------------- graph build ----------------
__global__ void zero_kernel() {
    int i = blockIdx.x * blockDim.x + threadIdx.x;
    if (i < N_NODES) { g_cnt[i] = 0; g_outdeg[i] = 0; }
}

__global__ void build_kernel(const int* __restrict__ src, const int* __restrict__ dst) {
    int e = blockIdx.x * blockDim.x + threadIdx.x;
    if (e >= N_EDGES) return;
    int s = src[e], d = dst[e];
    atomicAdd(&g_outdeg[s], 1);
    int pos = atomicAdd(&g_cnt[d], 1);
    if (pos < CAP) g_csr[(size_t)d * CAP + pos] = s;
}

__global__ void norm_kernel() {
    int i = blockIdx.x * blockDim.x + threadIdx.x;
    if (i >= N_NODES) return;
    int od = g_outdeg[i]; if (od < 1) od = 1;
    int id = g_cnt[i];    if (id < 1) id = 1;
    g_nsrc[i] = rsqrtf((float)od);
    g_ndst[i] = rsqrtf((float)id);
}

// ---------------- SGEMM: Y[m, 0:BN] = nsrc[m] * sum_k A[m,k] * W[k,n]   (K=128 fixed) ----------------
template <int BN>
__global__ __launch_bounds__(256) void gemm_kernel(const float* __restrict__ A,
                                                   const float* __restrict__ W,
                                                   float* __restrict__ Y) {
    constexpr int BM = 64, BK = 16, TM = 4, TN = BN / 16;
    __shared__ float Ast[BK][BM];      // A tile, transposed
    __shared__ float Bs[BK][BN];       // W tile

    const int tid = threadIdx.x;            // 256 threads
    const int tx  = tid & 15;                // 0..15 -> BN/TN columns groups
    const int ty  = tid >> 4;                // 0..15 -> BM/TM row groups
    const int m0  = blockIdx.x * BM;

    float acc[TM][TN];
#pragma unroll
    for (int i = 0; i < TM; i++)
#pragma unroll
        for (int j = 0; j < TN; j++) acc[i][j] = 0.f;

    const int lr = tid >> 2;                 // 0..63 : A row within tile
    const int lk = (tid & 3) * 4;            // 0,4,8,12 : k offset (float4)

    for (int kt = 0; kt < 128; kt += BK) {
        // load A tile (guard tail block), store transposed
        float4 av = make_float4(0.f, 0.f, 0.f, 0.f);
        int row = m0 + lr;
        if (row < N_NODES)
            av = *(const float4*)(A + (size_t)row * 128 + kt + lk);
        Ast[lk + 0][lr] = av.x;
        Ast[lk + 1][lr] = av.y;
        Ast[lk + 2][lr] = av.z;
        Ast[lk + 3][lr] = av.w;

        // load W tile
        constexpr int NLOAD = (BK * BN / 4) / 256;   // 2 for BN=128, 1 for BN=64
#pragma unroll
        for (int t = 0; t < NLOAD; t++) {
            int slot = tid + t * 256;
            int bk = slot / (BN / 4);
            int bc = (slot % (BN / 4)) * 4;
            *(float4*)&Bs[bk][bc] = *(const float4*)(W + (size_t)(kt + bk) * BN + bc);
        }
        __syncthreads();

#pragma unroll
        for (int k = 0; k < BK; k++) {
            float4 a4 = *(const float4*)&Ast[k][ty * TM];
            float a[TM] = {a4.x, a4.y, a4.z, a4.w};
            float b[TN];
#pragma unroll
            for (int j = 0; j < TN; j += 4) {
                float4 b4 = *(const float4*)&Bs[k][tx * TN + j];
                b[j] = b4.x; b[j + 1] = b4.y; b[j + 2] = b4.z; b[j + 3] = b4.w;
            }
#pragma unroll
            for (int i = 0; i < TM; i++)
#pragma unroll
                for (int j = 0; j < TN; j++)
                    acc[i][j] = fmaf(a[i], b[j], acc[i][j]);
        }
        __syncthreads();
    }

#pragma unroll
    for (int i = 0; i < TM; i++) {
        int row = m0 + ty * TM + i;
        if (row < N_NODES) {
            float s = g_nsrc[row];
#pragma unroll
            for (int j = 0; j < TN; j += 4) {
                float4 v = make_float4(acc[i][j] * s, acc[i][j + 1] * s,
                                       acc[i][j + 2] * s, acc[i][j + 3] * s);
                *(float4*)(Y + (size_t)row * BN + tx * TN + j) = v;
            }
        }
    }
}

// ---------------- aggregation, DIM=128: out[n] = relu(ndst[n] * sum_{s in csr[n]} y[s] + b) ----------------
__global__ __launch_bounds__(256) void agg128_kernel(const float* __restrict__ y,
                                                     float* __restrict__ out,
                                                     const float* __restrict__ bias) {
    int gw   = (blockIdx.x * blockDim.x + threadIdx.x) >> 5;  // node = global warp id
    int lane = threadIdx.x & 31;
    if (gw >= N_NODES) return;

    int c = g_cnt[gw]; if (c > CAP) c = CAP;
    const int* lst = g_csr + (size_t)gw * CAP;
    const float4* y4 = (const float4*)y;

    float4 acc = make_float4(0.f, 0.f, 0.f, 0.f);
    int i = 0;
    for (; i + 4 <= c; i += 4) {
        int s0 = lst[i], s1 = lst[i + 1], s2 = lst[i + 2], s3 = lst[i + 3];
        float4 v0 = y4[(size_t)s0 * 32 + lane];
        float4 v1 = y4[(size_t)s1 * 32 + lane];
        float4 v2 = y4[(size_t)s2 * 32 + lane];
        float4 v3 = y4[(size_t)s3 * 32 + lane];
        acc.x += (v0.x + v1.x) + (v2.x + v3.x);
        acc.y += (v0.y + v1.y) + (v2.y + v3.y);
        acc.z += (v0.z + v1.z) + (v2.z + v3.z);
        acc.w += (v0.w + v1.w) + (v2.w + v3.w);
    }
    for (; i < c; i++) {
        float4 v = y4[(size_t)lst[i] * 32 + lane];
        acc.x += v.x; acc.y += v.y; acc.z += v.z; acc.w += v.w;
    }

    float nd = g_ndst[gw];
    float4 b = ((const float4*)bias)[lane];
    float4 r;
    r.x = fmaxf(fmaf(acc.x, nd, b.x), 0.f);
    r.y = fmaxf(fmaf(acc.y, nd, b.y), 0.f);
    r.z = fmaxf(fmaf(acc.z, nd, b.z), 0.f);
    r.w = fmaxf(fmaf(acc.w, nd, b.w), 0.f);
    ((float4*)out)[(size_t)gw * 32 + lane] = r;
}

// ---------------- aggregation DIM=64 + fused log_softmax (final layer) ----------------
__global__ __launch_bounds__(256) void agg64_lsm_kernel(const float* __restrict__ y,
                                                        float* __restrict__ out,
                                                        const float* __restrict__ bias) {
    int gw   = (blockIdx.x * blockDim.x + threadIdx.x) >> 5;
    int lane = threadIdx.x & 31;
    if (gw >= N_NODES) return;

    int c = g_cnt[gw]; if (c > CAP) c = CAP;
    const int* lst = g_csr + (size_t)gw * CAP;
    const float2* y2 = (const float2*)y;

    float2 acc = make_float2(0.f, 0.f);
    int i = 0;
    for (; i + 4 <= c; i += 4) {
        int s0 = lst[i], s1 = lst[i + 1], s2 = lst[i + 2], s3 = lst[i + 3];
        float2 v0 = y2[(size_t)s0 * 32 + lane];
        float2 v1 = y2[(size_t)s1 * 32 + lane];
        float2 v2 = y2[(size_t)s2 * 32 + lane];
        float2 v3 = y2[(size_t)s3 * 32 + lane];
        acc.x += (v0.x + v1.x) + (v2.x + v3.x);
        acc.y += (v0.y + v1.y) + (v2.y + v3.y);
    }
    for (; i < c; i++) {
        float2 v = y2[(size_t)lst[i] * 32 + lane];
        acc.x += v.x; acc.y += v.y;
    }

    float nd = g_ndst[gw];
    float2 b = ((const float2*)bias)[lane];
    float vx = fmaxf(fmaf(acc.x, nd, b.x), 0.f);
    float vy = fmaxf(fmaf(acc.y, nd, b.y), 0.f);

    // warp-wide log_softmax over 64 values (2 per lane)
    float m = fmaxf(vx, vy);
#pragma unroll
    for (int off = 16; off > 0; off >>= 1)
        m = fmaxf(m, __shfl_xor_sync(0xffffffffu, m, off));
    float s = expf(vx - m) + expf(vy - m);
#pragma unroll
    for (int off = 16; off > 0; off >>= 1)
        s += __shfl_xor_sync(0xffffffffu, s, off);
    float l = m + logf(s);

    float2 o = make_float2(vx - l, vy - l);
    ((float2*)out)[(size_t)gw * 32 + lane] = o;
}

// ---------------- launch ----------------
extern "C" void kernel_launch(void* const* d_in, const int* in_sizes, int n_in,
                              void* d_out, int out_size) {
    const float* feats = (const float*)d_in[0];
    const float* W0 = (const float*)d_in[1];
    const float* b0 = (const float*)d_in[2];
    const float* W1 = (const float*)d_in[3];
    const float* b1 = (const float*)d_in[4];
    const float* W2 = (const float*)d_in[5];
    const float* b2 = (const float*)d_in[6];
    const int*  src = (const int*)d_in[7];
    const int*  dst = (const int*)d_in[8];
    float* out = (float*)d_out;

    float *yp, *hp;
    cudaGetSymbolAddress((void**)&yp, g_y);
    cudaGetSymbolAddress((void**)&hp, g_h);

    const int NTHROW = 256;
    int nodeBlocks = (N_NODES + NTHROW - 1) / NTHROW;          // 391
    int edgeBlocks = (N_EDGES + NTHROW - 1) / NTHROW;          // 6250
    int gemmBlocks = (N_NODES + 63) / 64;                      // 1563
    int warpBlocks = (N_NODES * 32 + NTHROW - 1) / NTHROW;     // 12500

    // graph structure + norms (recomputed every call: deterministic work)
    zero_kernel<<<nodeBlocks, NTHROW>>>();
    build_kernel<<<edgeBlocks, NTHROW>>>(src, dst);
    norm_kernel<<<nodeBlocks, NTHROW>>>();

    // layer 1: feats -> y -> h
    gemm_kernel<128><<<gemmBlocks, NTHROW>>>(feats, W0, yp);
    agg128_kernel<<<warpBlocks, NTHROW>>>(yp, hp, b0);

    // layer 2: h -> y -> h
    gemm_kernel<128><<<gemmBlocks, NTHROW>>>(hp, W1, yp);
    agg128_kernel<<<warpBlocks, NTHROW>>>(yp, hp, b1);

    // layer 3 (64-wide) + log_softmax: h -> y -> out
    gemm_kernel<64><<<gemmBlocks, NTHROW>>>(hp, W2, yp);
    agg64_lsm_kernel<<<warpBlocks, NTHROW>>>(yp, out, b2);
}

// round 2
// speedup vs baseline: 1.0764x; 1.0764x over previous
#include <cuda_runtime.h>
#include <math.h>

#define N_NODES 100000
#define N_EDGES 1600000
#define CAP 96   // max in-degree kept per node; Poisson(16) tail beyond 96 is ~1e-40

// ---------------- static device scratch (no allocations allowed) ----------------
__device__ float g_y[(size_t)N_NODES * 128];   // post-GEMM features (pre-aggregation)
__device__ float g_h[(size_t)N_NODES * 128];   // post-layer features
__device__ int   g_csr[(size_t)N_NODES * CAP]; // incoming src lists, bucketed by dst
__device__ int   g_cnt[N_NODES];               // in-degree (also CSR fill counter)
__device__ int   g_outdeg[N_NODES];            // out-degree
__device__ float g_nsrc[N_NODES];              // out_deg^-1/2 (clipped)
__device__ float g_ndst[N_NODES];              // in_deg^-1/2 (clipped)

// ---------------- graph build ----------------
__global__ void zero_kernel() {
    int i = blockIdx.x * blockDim.x + threadIdx.x;
    if (i < N_NODES) { g_cnt[i] = 0; g_outdeg[i] = 0; }
}

__global__ void build_kernel(const int* __restrict__ src, const int* __restrict__ dst) {
    int e = blockIdx.x * blockDim.x + threadIdx.x;
    if (e >= N_EDGES) return;
    int s = src[e], d = dst[e];
    atomicAdd(&g_outdeg[s], 1);
    int pos = atomicAdd(&g_cnt[d], 1);
    if (pos < CAP) g_csr[(size_t)d * CAP + pos] = s;
}

__global__ void norm_kernel() {
    int i = blockIdx.x * blockDim.x + threadIdx.x;
    if (i >= N_NODES) return;
    int od = g_outdeg[i]; if (od < 1) od = 1;
    int id = g_cnt[i];    if (id < 1) id = 1;
    g_nsrc[i] = rsqrtf((float)od);
    g_ndst[i] = rsqrtf((float)id);
}

// ---------------- SGEMM: Y[m, 0:BN] = nsrc[m] * (A[m,:] @ W[:,0:BN]),  K = 128 fixed ----
// BM=128 x BN block tile, 8x(4*NCG) register tile per thread, 256 threads,
// double-buffered SMEM with register prefetch. Conflict-free fragment layout.
template <int BN>
__global__ __launch_bounds__(256, 2) void gemm2_kernel(const float* __restrict__ A,
                                                       const float* __restrict__ W,
                                                       float* __restrict__ Y) {
    constexpr int BM = 128, BK = 16;
    constexpr int NCG = BN / 64;           // column groups: 2 for BN=128, 1 for BN=64
    constexpr int TN = 4 * NCG;

    __shared__ float As[2][BK][BM + 4];    // transposed A tile (+4 pad: keeps 16B align, cuts STS conflicts)
    __shared__ float Bs[2][BK][BN];

    const int tid = threadIdx.x;
    const int tx  = tid & 15;              // 16 col positions
    const int ty  = tid >> 4;              // 16 row positions
    const int m0  = blockIdx.x * BM;

    // global A load mapping: 2 float4 per thread per stage
    const int arow = tid >> 2;             // 0..63
    const int akk  = (tid & 3) << 2;       // 0,4,8,12
    // global B load mapping
    const int bk0 = tid / (BN / 4);        // BN=128: 0..7 ; BN=64: 0..15
    const int bc0 = (tid % (BN / 4)) * 4;

    const int r0 = m0 + arow;
    const int r1 = r0 + 64;
    const bool v0 = r0 < N_NODES;
    const bool v1 = r1 < N_NODES;

    float4 ra0, ra1, rb0, rb1;
    const float4 fz = make_float4(0.f, 0.f, 0.f, 0.f);

#define LOAD_TILE(KT)                                                                   \
    {                                                                                   \
        ra0 = v0 ? *(const float4*)(A + (size_t)r0 * 128 + (KT) + akk) : fz;            \
        ra1 = v1 ? *(const float4*)(A + (size_t)r1 * 128 + (KT) + akk) : fz;            \
        rb0 = *(const float4*)(W + (size_t)((KT) + bk0) * BN + bc0);                    \
        if (NCG == 2) rb1 = *(const float4*)(W + (size_t)((KT) + bk0 + 8) * BN + bc0);  \
    }

#define STORE_TILE(BUF)                                                                 \
    {                                                                                   \
        As[BUF][akk + 0][arow] = ra0.x;  As[BUF][akk + 1][arow] = ra0.y;                \
        As[BUF][akk + 2][arow] = ra0.z;  As[BUF][akk + 3][arow] = ra0.w;                \
        As[BUF][akk + 0][arow + 64] = ra1.x;  As[BUF][akk + 1][arow + 64] = ra1.y;      \
        As[BUF][akk + 2][arow + 64] = ra1.z;  As[BUF][akk + 3][arow + 64] = ra1.w;      \
        *(float4*)&Bs[BUF][bk0][bc0] = rb0;                                             \
        if (NCG == 2) *(float4*)&Bs[BUF][bk0 + 8][bc0] = rb1;                           \
    }

    float acc[8][TN];
#pragma unroll
    for (int i = 0; i < 8; i++)
#pragma unroll
        for (int j = 0; j < TN; j++) acc[i][j] = 0.f;

    LOAD_TILE(0);
    STORE_TILE(0);
    __syncthreads();

#pragma unroll
    for (int kt = 0; kt < 8; kt++) {
        const int buf = kt & 1;
        if (kt < 7) LOAD_TILE((kt + 1) * BK);

#pragma unroll
        for (int k = 0; k < BK; k++) {
            float4 a0 = *(const float4*)&As[buf][k][ty * 4];
            float4 a1 = *(const float4*)&As[buf][k][64 + ty * 4];
            float4 b0 = *(const float4*)&Bs[buf][k][tx * 4];
            float av[8] = {a0.x, a0.y, a0.z, a0.w, a1.x, a1.y, a1.z, a1.w};
            float bv[TN];
            bv[0] = b0.x; bv[1] = b0.y; bv[2] = b0.z; bv[3] = b0.w;
            if (NCG == 2) {
                float4 b1 = *(const float4*)&Bs[buf][k][64 + tx * 4];
                bv[4] = b1.x; bv[5] = b1.y; bv[6] = b1.z; bv[7] = b1.w;
            }
#pragma unroll
            for (int i = 0; i < 8; i++)
#pragma unroll
                for (int j = 0; j < TN; j++)
                    acc[i][j] = fmaf(av[i], bv[j], acc[i][j]);
        }

        if (kt < 7) {
            STORE_TILE(buf ^ 1);
            __syncthreads();
        }
    }

#undef LOAD_TILE
#undef STORE_TILE

    // epilogue: scale by nsrc, write
#pragma unroll
    for (int g = 0; g < 2; g++) {
#pragma unroll
        for (int i = 0; i < 4; i++) {
            int row = m0 + g * 64 + ty * 4 + i;
            if (row >= N_NODES) continue;
            float s = g_nsrc[row];
            int ri = g * 4 + i;
            float4 o0 = make_float4(acc[ri][0] * s, acc[ri][1] * s,
                                    acc[ri][2] * s, acc[ri][3] * s);
            *(float4*)(Y + (size_t)row * BN + tx * 4) = o0;
            if (NCG == 2) {
                float4 o1 = make_float4(acc[ri][4] * s, acc[ri][5] * s,
                                        acc[ri][6] * s, acc[ri][7] * s);
                *(float4*)(Y + (size_t)row * BN + 64 + tx * 4) = o1;
            }
        }
    }
}

// ---------------- aggregation, DIM=128: out[n] = relu(ndst[n] * sum_{s in csr[n]} y[s] + b) ----------------
__global__ __launch_bounds__(256) void agg128_kernel(const float* __restrict__ y,
                                                     float* __restrict__ out,
                                                     const float* __restrict__ bias) {
    int gw   = (blockIdx.x * blockDim.x + threadIdx.x) >> 5;  // node = global warp id
    int lane = threadIdx.x & 31;
    if (gw >= N_NODES) return;

    int c = g_cnt[gw]; if (c > CAP) c = CAP;
    const int* lst = g_csr + (size_t)gw * CAP;
    const float4* y4 = (const float4*)y;

    float4 acc = make_float4(0.f, 0.f, 0.f, 0.f);
    int i = 0;
    for (; i + 4 <= c; i += 4) {
        int s0 = lst[i], s1 = lst[i + 1], s2 = lst[i + 2], s3 = lst[i + 3];
        float4 v0 = y4[(size_t)s0 * 32 + lane];
        float4 v1 = y4[(size_t)s1 * 32 + lane];
        float4 v2 = y4[(size_t)s2 * 32 + lane];
        float4 v3 = y4[(size_t)s3 * 32 + lane];
        acc.x += (v0.x + v1.x) + (v2.x + v3.x);
        acc.y += (v0.y + v1.y) + (v2.y + v3.y);
        acc.z += (v0.z + v1.z) + (v2.z + v3.z);
        acc.w += (v0.w + v1.w) + (v2.w + v3.w);
    }
    for (; i < c; i++) {
        float4 v = y4[(size_t)lst[i] * 32 + lane];
        acc.x += v.x; acc.y += v.y; acc.z += v.z; acc.w += v.w;
    }

    float nd = g_ndst[gw];
    float4 b = ((const float4*)bias)[lane];
    float4 r;
    r.x = fmaxf(fmaf(acc.x, nd, b.x), 0.f);
    r.y = fmaxf(fmaf(acc.y, nd, b.y), 0.f);
    r.z = fmaxf(fmaf(acc.z, nd, b.z), 0.f);
    r.w = fmaxf(fmaf(acc.w, nd, b.w), 0.f);
    ((float4*)out)[(size_t)gw * 32 + lane] = r;
}

// ---------------- aggregation DIM=64 + fused log_softmax (final layer) ----------------
__global__ __launch_bounds__(256) void agg64_lsm_kernel(const float* __restrict__ y,
                                                        float* __restrict__ out,
                                                        const float* __restrict__ bias) {
    int gw   = (blockIdx.x * blockDim.x + threadIdx.x) >> 5;
    int lane = threadIdx.x & 31;
    if (gw >= N_NODES) return;

    int c = g_cnt[gw]; if (c > CAP) c = CAP;
    const int* lst = g_csr + (size_t)gw * CAP;
    const float2* y2 = (const float2*)y;

    float2 acc = make_float2(0.f, 0.f);
    int i = 0;
    for (; i + 4 <= c; i += 4) {
        int s0 = lst[i], s1 = lst[i + 1], s2 = lst[i + 2], s3 = lst[i + 3];
        float2 v0 = y2[(size_t)s0 * 32 + lane];
        float2 v1 = y2[(size_t)s1 * 32 + lane];
        float2 v2 = y2[(size_t)s2 * 32 + lane];
        float2 v3 = y2[(size_t)s3 * 32 + lane];
        acc.x += (v0.x + v1.x) + (v2.x + v3.x);
        acc.y += (v0.y + v1.y) + (v2.y + v3.y);
    }
    for (; i < c; i++) {
        float2 v = y2[(size_t)lst[i] * 32 + lane];
        acc.x += v.x; acc.y += v.y;
    }

    float nd = g_ndst[gw];
    float2 b = ((const float2*)bias)[lane];
    float vx = fmaxf(fmaf(acc.x, nd, b.x), 0.f);
    float vy = fmaxf(fmaf(acc.y, nd, b.y), 0.f);

    // warp-wide log_softmax over 64 values (2 per lane)
    float m = fmaxf(vx, vy);
#pragma unroll
    for (int off = 16; off > 0; off >>= 1)
        m = fmaxf(m, __shfl_xor_sync(0xffffffffu, m, off));
    float s = expf(vx - m) + expf(vy - m);
#pragma unroll
    for (int off = 16; off > 0; off >>= 1)
        s += __shfl_xor_sync(0xffffffffu, s, off);
    float l = m + logf(s);

    float2 o = make_float2(vx - l, vy - l);
    ((float2*)out)[(size_t)gw * 32 + lane] = o;
}

// ---------------- launch ----------------
extern "C" void kernel_launch(void* const* d_in, const int* in_sizes, int n_in,
                              void* d_out, int out_size) {
    const float* feats = (const float*)d_in[0];
    const float* W0 = (const float*)d_in[1];
    const float* b0 = (const float*)d_in[2];
    const float* W1 = (const float*)d_in[3];
    const float* b1 = (const float*)d_in[4];
    const float* W2 = (const float*)d_in[5];
    const float* b2 = (const float*)d_in[6];
    const int*  src = (const int*)d_in[7];
    const int*  dst = (const int*)d_in[8];
    float* out = (float*)d_out;

    float *yp, *hp;
    cudaGetSymbolAddress((void**)&yp, g_y);
    cudaGetSymbolAddress((void**)&hp, g_h);

    const int NT = 256;
    int nodeBlocks = (N_NODES + NT - 1) / NT;           // 391
    int edgeBlocks = (N_EDGES + NT - 1) / NT;           // 6250
    int gemmBlocks = (N_NODES + 127) / 128;             // 782
    int warpBlocks = (N_NODES * 32 + NT - 1) / NT;      // 12500

    // graph structure + norms (recomputed every call: deterministic work)
    zero_kernel<<<nodeBlocks, NT>>>();
    build_kernel<<<edgeBlocks, NT>>>(src, dst);
    norm_kernel<<<nodeBlocks, NT>>>();

    // layer 1: feats -> y -> h
    gemm2_kernel<128><<<gemmBlocks, NT>>>(feats, W0, yp);
    agg128_kernel<<<warpBlocks, NT>>>(yp, hp, b0);

    // layer 2: h -> y -> h
    gemm2_kernel<128><<<gemmBlocks, NT>>>(hp, W1, yp);
    agg128_kernel<<<warpBlocks, NT>>>(yp, hp, b1);

    // layer 3 (64-wide) + log_softmax: h -> y -> out
    gemm2_kernel<64><<<gemmBlocks, NT>>>(hp, W2, yp);
    agg64_lsm_kernel<<<warpBlocks, NT>>>(yp, out, b2);
}

// round 6
// speedup vs baseline: 2.1194x; 1.9690x over previous
#include <cuda_runtime.h>
#include <cuda_fp16.h>
#include <stdint.h>
#include <math.h>

#define N_NODES 100000
#define N_EDGES 1600000
#define CAP 96

// ---------------- static device scratch ----------------
__device__ __half g_y16[(size_t)N_NODES * 128];
__device__ __half g_h16[(size_t)N_NODES * 128];
__device__ __half g_f16[(size_t)N_NODES * 128];
__device__ __half g_w0h[128 * 128];
__device__ __half g_w1h[128 * 128];
__device__ __half g_w2h[128 * 64];
__device__ int   g_csr[(size_t)N_NODES * CAP];
__device__ int   g_cnt[N_NODES];
__device__ int   g_outdeg[N_NODES];
__device__ float g_nsrc[N_NODES];
__device__ float g_ndst[N_NODES];

// ---------------- graph build ----------------
__global__ void zero_kernel() {
    int i = blockIdx.x * blockDim.x + threadIdx.x;
    if (i < N_NODES) { g_cnt[i] = 0; g_outdeg[i] = 0; }
}

__global__ void build_kernel(const int* __restrict__ src, const int* __restrict__ dst) {
    int e = blockIdx.x * blockDim.x + threadIdx.x;
    if (e >= N_EDGES) return;
    int s = src[e];
    int d = dst[e];
    atomicAdd(&g_outdeg[s], 1);
    int pos = atomicAdd(&g_cnt[d], 1);
    if (pos < CAP) g_csr[(size_t)d * CAP + pos] = s;
}

__global__ void norm_kernel() {
    int i = blockIdx.x * blockDim.x + threadIdx.x;
    if (i >= N_NODES) return;
    int od = g_outdeg[i]; if (od < 1) od = 1;
    int id = g_cnt[i];    if (id < 1) id = 1;
    g_nsrc[i] = rsqrtf((float)od);
    g_ndst[i] = rsqrtf((float)id);
}

// ---------------- fp32 -> fp16 conversion ----------------
__global__ void cvt_kernel(const float* __restrict__ in, __half* __restrict__ out, int n4) {
    int i = blockIdx.x * blockDim.x + threadIdx.x;
    if (i >= n4) return;
    float4 v = ((const float4*)in)[i];
    __half2 lo = __floats2half2_rn(v.x, v.y);
    __half2 hi = __floats2half2_rn(v.z, v.w);
    uint2 o;
    o.x = *(uint32_t*)&lo;
    o.y = *(uint32_t*)&hi;
    ((uint2*)out)[i] = o;
}

// ---------------- tensor-core helpers ----------------
// NOTE: all inline-PTX bracket lists are written with spaces ("{ %0")
// to avoid template-render digraphs in the bench pipeline.
__device__ __forceinline__ uint32_t s2u(const void* p) {
    uint32_t a;
    asm("{ .reg .u64 t; cvta.to.shared.u64 t, %1; cvt.u32.u64 %0, t; }" : "=r"(a) : "l"(p));
    return a;
}

__device__ __forceinline__ void ldsm_x4(uint32_t& r0, uint32_t& r1, uint32_t& r2, uint32_t& r3,
                                        uint32_t addr) {
    asm volatile("ldmatrix.sync.aligned.m8n8.x4.shared.b16 { %0, %1, %2, %3 }, [ %4 ];"
                 : "=r"(r0), "=r"(r1), "=r"(r2), "=r"(r3) : "r"(addr));
}

__device__ __forceinline__ void ldsm_x4_t(uint32_t& r0, uint32_t& r1, uint32_t& r2, uint32_t& r3,
                                          uint32_t addr) {
    asm volatile("ldmatrix.sync.aligned.m8n8.x4.trans.shared.b16 { %0, %1, %2, %3 }, [ %4 ];"
                 : "=r"(r0), "=r"(r1), "=r"(r2), "=r"(r3) : "r"(addr));
}

__device__ __forceinline__ void mma_16816(float* c, const uint32_t* a, const uint32_t* b) {
    asm volatile(
        "mma.sync.aligned.m16n8k16.row.col.f32.f16.f16.f32 "
        "{ %0, %1, %2, %3 }, { %4, %5, %6, %7 }, { %8, %9 }, { %0, %1, %2, %3 };"
        : "+f"(c[0]), "+f"(c[1]), "+f"(c[2]), "+f"(c[3])
        : "r"(a[0]), "r"(a[1]), "r"(a[2]), "r"(a[3]), "r"(b[0]), "r"(b[1]));
}

// ---------------- HGEMM: Y[m,0:BN] = half( nsrc[m] * (A[m,:] @ W[:,0:BN]) ), K=128 ----
// BM=128, whole K in SMEM, one sync. 8 warps: 2 (m) x 4 (n).
template <int BN>
__global__ __launch_bounds__(256) void hgemm_kernel(const __half* __restrict__ A,
                                                    const __half* __restrict__ W,
                                                    __half* __restrict__ Y) {
    extern __shared__ __align__(16) char dynbuf[];
    const int LDA = 136;
    const int LDB = BN + 8;
    __half* As = (__half*)dynbuf;               // [128][136]
    __half* Bs = (__half*)dynbuf + 128 * LDA;   // [128][LDB]

    const int tid = threadIdx.x;
    const int m0  = blockIdx.x * 128;

    // load A tile (row-major [m][k]); zero-fill OOB rows
    {
        const uint4 z = make_uint4(0u, 0u, 0u, 0u);
#pragma unroll
        for (int i = 0; i < 8; i++) {
            int slot = tid + i * 256;            // 2048 slots of 8 halves
            int row = slot >> 4;
            int col = (slot & 15) * 8;
            int gr = m0 + row;
            uint4 v = z;
            if (gr < N_NODES) v = *(const uint4*)(A + (size_t)gr * 128 + col);
            *(uint4*)(As + row * LDA + col) = v;
        }
    }
    // load B tile (row-major [k][n])
    {
        const int SLOTS = 128 * BN / 8;
#pragma unroll
        for (int i = 0; i < SLOTS / 256; i++) {
            int slot = tid + i * 256;
            int row = slot / (BN / 8);
            int col = (slot % (BN / 8)) * 8;
            *(uint4*)(Bs + row * LDB + col) = *(const uint4*)(W + (size_t)row * BN + col);
        }
    }
    __syncthreads();

    const int w = tid >> 5;
    const int lane = tid & 31;
    const int WN = (BN == 128) ? 32 : 16;
    const int NF = WN / 8;
    const int wm = (w & 1) * 64;
    const int wn = (w >> 1) * WN;

    float c[4][4][4];   // [mi][nj<=NF][quad]
#pragma unroll
    for (int mi = 0; mi < 4; mi++)
#pragma unroll
        for (int nj = 0; nj < 4; nj++)
#pragma unroll
            for (int q = 0; q < 4; q++) c[mi][nj][q] = 0.f;

    const int lr = lane & 15;
    const int lc = (lane >> 4) << 3;

#pragma unroll
    for (int kk = 0; kk < 8; kk++) {
        const int k0 = kk * 16;
        uint32_t a[4][4];
#pragma unroll
        for (int mi = 0; mi < 4; mi++) {
            uint32_t addr = s2u(As + (wm + mi * 16 + lr) * LDA + k0 + lc);
            ldsm_x4(a[mi][0], a[mi][1], a[mi][2], a[mi][3], addr);
        }
        uint32_t b[4][2];
#pragma unroll
        for (int bj = 0; bj < NF / 2; bj++) {
            uint32_t r0, r1, r2, r3;
            uint32_t addr = s2u(Bs + (k0 + lr) * LDB + wn + bj * 16 + lc);
            ldsm_x4_t(r0, r1, r2, r3, addr);
            b[bj * 2][0] = r0;     b[bj * 2][1] = r1;
            b[bj * 2 + 1][0] = r2; b[bj * 2 + 1][1] = r3;
        }
#pragma unroll
        for (int mi = 0; mi < 4; mi++)
#pragma unroll
            for (int nj = 0; nj < NF; nj++)
                mma_16816(c[mi][nj], a[mi], b[nj]);
    }

    // epilogue: scale by nsrc, convert fp16, store
    const int qr = lane >> 2;
    const int qc = (lane & 3) * 2;
#pragma unroll
    for (int mi = 0; mi < 4; mi++) {
        int r0 = m0 + wm + mi * 16 + qr;
        int r1 = r0 + 8;
        float s0 = 0.f;
        float s1 = 0.f;
        if (r0 < N_NODES) s0 = g_nsrc[r0];
        if (r1 < N_NODES) s1 = g_nsrc[r1];
#pragma unroll
        for (int nj = 0; nj < NF; nj++) {
            int col = wn + nj * 8 + qc;
            if (r0 < N_NODES) {
                __half2 h = __floats2half2_rn(c[mi][nj][0] * s0, c[mi][nj][1] * s0);
                *(uint32_t*)(Y + (size_t)r0 * BN + col) = *(uint32_t*)&h;
            }
            if (r1 < N_NODES) {
                __half2 h = __floats2half2_rn(c[mi][nj][2] * s1, c[mi][nj][3] * s1);
                *(uint32_t*)(Y + (size_t)r1 * BN + col) = *(uint32_t*)&h;
            }
        }
    }
}

// ---------------- aggregation, DIM=128 (fp16 in, fp32 accum, fp16 out) ----------------
__global__ __launch_bounds__(256) void agg128h_kernel(const __half* __restrict__ y,
                                                      __half* __restrict__ out,
                                                      const float* __restrict__ bias) {
    int gw   = (blockIdx.x * blockDim.x + threadIdx.x) >> 5;
    int lane = threadIdx.x & 31;
    if (gw >= N_NODES) return;

    int c = g_cnt[gw]; if (c > CAP) c = CAP;
    const int* lst = g_csr + (size_t)gw * CAP;
    const uint2* y2 = (const uint2*)y;   // 4 halves per lane

    float ax = 0.f, ay = 0.f, az = 0.f, aw = 0.f;
#pragma unroll 4
    for (int i = 0; i < c; i++) {
        uint2 v = y2[(size_t)lst[i] * 32 + lane];
        float2 f0 = __half22float2(*(const __half2*)&v.x);
        float2 f1 = __half22float2(*(const __half2*)&v.y);
        ax += f0.x; ay += f0.y; az += f1.x; aw += f1.y;
    }

    float nd = g_ndst[gw];
    float4 b = ((const float4*)bias)[lane];
    float rx = fmaxf(fmaf(ax, nd, b.x), 0.f);
    float ry = fmaxf(fmaf(ay, nd, b.y), 0.f);
    float rz = fmaxf(fmaf(az, nd, b.z), 0.f);
    float rw = fmaxf(fmaf(aw, nd, b.w), 0.f);

    __half2 lo = __floats2half2_rn(rx, ry);
    __half2 hi = __floats2half2_rn(rz, rw);
    uint2 o;
    o.x = *(uint32_t*)&lo;
    o.y = *(uint32_t*)&hi;
    ((uint2*)out)[(size_t)gw * 32 + lane] = o;
}

// ---------------- aggregation DIM=64 + fused log_softmax (fp32 out) ----------------
__global__ __launch_bounds__(256) void agg64h_lsm_kernel(const __half* __restrict__ y,
                                                         float* __restrict__ out,
                                                         const float* __restrict__ bias) {
    int gw   = (blockIdx.x * blockDim.x + threadIdx.x) >> 5;
    int lane = threadIdx.x & 31;
    if (gw >= N_NODES) return;

    int c = g_cnt[gw]; if (c > CAP) c = CAP;
    const int* lst = g_csr + (size_t)gw * CAP;
    const uint32_t* y1 = (const uint32_t*)y;   // 2 halves per lane

    float ax = 0.f, ay = 0.f;
#pragma unroll 4
    for (int i = 0; i < c; i++) {
        uint32_t v = y1[(size_t)lst[i] * 32 + lane];
        float2 f = __half22float2(*(const __half2*)&v);
        ax += f.x; ay += f.y;
    }

    float nd = g_ndst[gw];
    float2 b = ((const float2*)bias)[lane];
    float vx = fmaxf(fmaf(ax, nd, b.x), 0.f);
    float vy = fmaxf(fmaf(ay, nd, b.y), 0.f);

    float m = fmaxf(vx, vy);
#pragma unroll
    for (int off = 16; off > 0; off >>= 1)
        m = fmaxf(m, __shfl_xor_sync(0xffffffffu, m, off));
    float s = expf(vx - m) + expf(vy - m);
#pragma unroll
    for (int off = 16; off > 0; off >>= 1)
        s += __shfl_xor_sync(0xffffffffu, s, off);
    float l = m + logf(s);

    ((float2*)out)[(size_t)gw * 32 + lane] = make_float2(vx - l, vy - l);
}

// ---------------- launch ----------------
extern "C" void kernel_launch(void* const* d_in, const int* in_sizes, int n_in,
                              void* d_out, int out_size) {
    const float* feats = (const float*)d_in[0];
    const float* W0 = (const float*)d_in[1];
    const float* b0 = (const float*)d_in[2];
    const float* W1 = (const float*)d_in[3];
    const float* b1 = (const float*)d_in[4];
    const float* W2 = (const float*)d_in[5];
    const float* b2 = (const float*)d_in[6];
    const int*  src = (const int*)d_in[7];
    const int*  dst = (const int*)d_in[8];
    float* out = (float*)d_out;

    __half* y16; cudaGetSymbolAddress((void**)&y16, g_y16);
    __half* h16; cudaGetSymbolAddress((void**)&h16, g_h16);
    __half* f16; cudaGetSymbolAddress((void**)&f16, g_f16);
    __half* w0h; cudaGetSymbolAddress((void**)&w0h, g_w0h);
    __half* w1h; cudaGetSymbolAddress((void**)&w1h, g_w1h);
    __half* w2h; cudaGetSymbolAddress((void**)&w2h, g_w2h);

    const int NT = 256;
    int nodeBlocks = (N_NODES + NT - 1) / NT;
    int edgeBlocks = (N_EDGES + NT - 1) / NT;
    int gemmBlocks = (N_NODES + 127) / 128;
    int warpBlocks = (N_NODES * 32 + NT - 1) / NT;

    const int SMEM128 = (128 * 136 + 128 * 136) * 2;   // 69632
    const int SMEM64  = (128 * 136 + 128 * 72) * 2;    // 53248
    cudaFuncSetAttribute(hgemm_kernel<128>, cudaFuncAttributeMaxDynamicSharedMemorySize, SMEM128);
    cudaFuncSetAttribute(hgemm_kernel<64>,  cudaFuncAttributeMaxDynamicSharedMemorySize, SMEM64);

    zero_kernel<<<nodeBlocks, NT>>>();
    build_kernel<<<edgeBlocks, NT>>>(src, dst);
    norm_kernel<<<nodeBlocks, NT>>>();

    int f4 = N_NODES * 128 / 4;
    cvt_kernel<<<(f4 + NT - 1) / NT, NT>>>(feats, f16, f4);
    cvt_kernel<<<(128 * 128 / 4 + NT - 1) / NT, NT>>>(W0, w0h, 128 * 128 / 4);
    cvt_kernel<<<(128 * 128 / 4 + NT - 1) / NT, NT>>>(W1, w1h, 128 * 128 / 4);
    cvt_kernel<<<(128 * 64 / 4 + NT - 1) / NT, NT>>>(W2, w2h, 128 * 64 / 4);

    hgemm_kernel<128><<<gemmBlocks, NT, SMEM128>>>(f16, w0h, y16);
    agg128h_kernel<<<warpBlocks, NT>>>(y16, h16, b0);

    hgemm_kernel<128><<<gemmBlocks, NT, SMEM128>>>(h16, w1h, y16);
    agg128h_kernel<<<warpBlocks, NT>>>(y16, h16, b1);

    hgemm_kernel<64><<<gemmBlocks, NT, SMEM64>>>(h16, w2h, y16);
    agg64h_lsm_kernel<<<warpBlocks, NT>>>(y16, out, b2);
}

// round 7
// speedup vs baseline: 2.4933x; 1.1764x over previous
#include <cuda_runtime.h>
#include <cuda_fp16.h>
#include <stdint.h>
#include <math.h>

#define N_NODES 100000
#define N_EDGES 1600000
#define CAP 96

// ---------------- static device scratch ----------------
__device__ __half g_y16[(size_t)N_NODES * 128];
__device__ __half g_h16[(size_t)N_NODES * 128];
__device__ __half g_w0h[128 * 128];
__device__ __half g_w1h[128 * 128];
__device__ __half g_w2h[128 * 64];
__device__ int   g_csr[(size_t)N_NODES * CAP];
__device__ int   g_cnt[N_NODES];
__device__ int   g_outdeg[N_NODES];
__device__ float g_nsrc[N_NODES];
__device__ float g_ndst[N_NODES];

// ---------------- graph build ----------------
__global__ void zero_kernel() {
    int i = blockIdx.x * blockDim.x + threadIdx.x;
    if (i < N_NODES) { g_cnt[i] = 0; g_outdeg[i] = 0; }
}

__global__ void build_kernel(const int* __restrict__ src, const int* __restrict__ dst) {
    int e = blockIdx.x * blockDim.x + threadIdx.x;
    if (e >= N_EDGES) return;
    int s = src[e];
    int d = dst[e];
    atomicAdd(&g_outdeg[s], 1);
    int pos = atomicAdd(&g_cnt[d], 1);
    if (pos < CAP) g_csr[(size_t)d * CAP + pos] = s;
}

__global__ void norm_kernel() {
    int i = blockIdx.x * blockDim.x + threadIdx.x;
    if (i >= N_NODES) return;
    int od = g_outdeg[i]; if (od < 1) od = 1;
    int id = g_cnt[i];    if (id < 1) id = 1;
    g_nsrc[i] = rsqrtf((float)od);
    g_ndst[i] = rsqrtf((float)id);
}

// ---------------- all three weight matrices fp32->fp16, one launch ----------------
__global__ void cvtw_kernel(const float* __restrict__ W0, const float* __restrict__ W1,
                            const float* __restrict__ W2,
                            __half* __restrict__ w0h, __half* __restrict__ w1h,
                            __half* __restrict__ w2h) {
    int i = blockIdx.x * blockDim.x + threadIdx.x;   // slot of 4 floats
    const float* src;
    __half* dst;
    int base;
    if (i < 4096)        { src = W0; dst = w0h; base = i; }
    else if (i < 8192)   { src = W1; dst = w1h; base = i - 4096; }
    else if (i < 10240)  { src = W2; dst = w2h; base = i - 8192; }
    else return;
    float4 v = ((const float4*)src)[base];
    __half2 lo = __floats2half2_rn(v.x, v.y);
    __half2 hi = __floats2half2_rn(v.z, v.w);
    uint2 o;
    o.x = *(uint32_t*)&lo;
    o.y = *(uint32_t*)&hi;
    ((uint2*)dst)[base] = o;
}

// ---------------- tensor-core helpers ----------------
// NOTE: inline-PTX bracket lists written with spaces to avoid template digraphs.
__device__ __forceinline__ uint32_t s2u(const void* p) {
    uint32_t a;
    asm("{ .reg .u64 t; cvta.to.shared.u64 t, %1; cvt.u32.u64 %0, t; }" : "=r"(a) : "l"(p));
    return a;
}

__device__ __forceinline__ void ldsm_x4(uint32_t& r0, uint32_t& r1, uint32_t& r2, uint32_t& r3,
                                        uint32_t addr) {
    asm volatile("ldmatrix.sync.aligned.m8n8.x4.shared.b16 { %0, %1, %2, %3 }, [ %4 ];"
                 : "=r"(r0), "=r"(r1), "=r"(r2), "=r"(r3) : "r"(addr));
}

__device__ __forceinline__ void ldsm_x4_t(uint32_t& r0, uint32_t& r1, uint32_t& r2, uint32_t& r3,
                                          uint32_t addr) {
    asm volatile("ldmatrix.sync.aligned.m8n8.x4.trans.shared.b16 { %0, %1, %2, %3 }, [ %4 ];"
                 : "=r"(r0), "=r"(r1), "=r"(r2), "=r"(r3) : "r"(addr));
}

__device__ __forceinline__ void mma_16816(float* c, const uint32_t* a, const uint32_t* b) {
    asm volatile(
        "mma.sync.aligned.m16n8k16.row.col.f32.f16.f16.f32 "
        "{ %0, %1, %2, %3 }, { %4, %5, %6, %7 }, { %8, %9 }, { %0, %1, %2, %3 };"
        : "+f"(c[0]), "+f"(c[1]), "+f"(c[2]), "+f"(c[3])
        : "r"(a[0]), "r"(a[1]), "r"(a[2]), "r"(a[3]), "r"(b[0]), "r"(b[1]));
}

// ---------------- HGEMM: Y[m,0:BN] = half( nsrc[m] * (A[m,:] @ W[:,0:BN]) ), K=128 ----
// BM=128, whole K in SMEM, one sync. 8 warps: 2 (m) x 4 (n).
// F32IN: A is fp32 (layer 1, converts on the fly); else A is fp16.
template <int BN, bool F32IN>
__global__ __launch_bounds__(256) void hgemm_kernel(const float* __restrict__ Af,
                                                    const __half* __restrict__ Ah,
                                                    const __half* __restrict__ W,
                                                    __half* __restrict__ Y) {
    extern __shared__ __align__(16) char dynbuf[];
    const int LDA = 136;
    const int LDB = BN + 8;
    __half* As = (__half*)dynbuf;               // [128][136]
    __half* Bs = (__half*)dynbuf + 128 * LDA;   // [128][LDB]

    const int tid = threadIdx.x;
    const int m0  = blockIdx.x * 128;

    // load A tile (row-major [m][k]); zero-fill OOB rows; fp32 path converts inline
    {
#pragma unroll
        for (int i = 0; i < 8; i++) {
            int slot = tid + i * 256;            // 2048 slots of 8 halves
            int row = slot >> 4;
            int col = (slot & 15) * 8;
            int gr = m0 + row;
            uint4 v = make_uint4(0u, 0u, 0u, 0u);
            if (gr < N_NODES) {
                if (F32IN) {
                    float4 lo = *(const float4*)(Af + (size_t)gr * 128 + col);
                    float4 hi = *(const float4*)(Af + (size_t)gr * 128 + col + 4);
                    __half2 h0 = __floats2half2_rn(lo.x, lo.y);
                    __half2 h1 = __floats2half2_rn(lo.z, lo.w);
                    __half2 h2 = __floats2half2_rn(hi.x, hi.y);
                    __half2 h3 = __floats2half2_rn(hi.z, hi.w);
                    v.x = *(uint32_t*)&h0; v.y = *(uint32_t*)&h1;
                    v.z = *(uint32_t*)&h2; v.w = *(uint32_t*)&h3;
                } else {
                    v = *(const uint4*)(Ah + (size_t)gr * 128 + col);
                }
            }
            *(uint4*)(As + row * LDA + col) = v;
        }
    }
    // load B tile (row-major [k][n])
    {
        const int SLOTS = 128 * BN / 8;
#pragma unroll
        for (int i = 0; i < SLOTS / 256; i++) {
            int slot = tid + i * 256;
            int row = slot / (BN / 8);
            int col = (slot % (BN / 8)) * 8;
            *(uint4*)(Bs + row * LDB + col) = *(const uint4*)(W + (size_t)row * BN + col);
        }
    }
    __syncthreads();

    const int w = tid >> 5;
    const int lane = tid & 31;
    const int WN = (BN == 128) ? 32 : 16;
    const int NF = WN / 8;
    const int wm = (w & 1) * 64;
    const int wn = (w >> 1) * WN;

    float c[4][4][4];
#pragma unroll
    for (int mi = 0; mi < 4; mi++)
#pragma unroll
        for (int nj = 0; nj < 4; nj++)
#pragma unroll
            for (int q = 0; q < 4; q++) c[mi][nj][q] = 0.f;

    const int lr = lane & 15;
    const int lc = (lane >> 4) << 3;

#pragma unroll
    for (int kk = 0; kk < 8; kk++) {
        const int k0 = kk * 16;
        uint32_t a[4][4];
#pragma unroll
        for (int mi = 0; mi < 4; mi++) {
            uint32_t addr = s2u(As + (wm + mi * 16 + lr) * LDA + k0 + lc);
            ldsm_x4(a[mi][0], a[mi][1], a[mi][2], a[mi][3], addr);
        }
        uint32_t b[4][2];
#pragma unroll
        for (int bj = 0; bj < NF / 2; bj++) {
            uint32_t r0, r1, r2, r3;
            uint32_t addr = s2u(Bs + (k0 + lr) * LDB + wn + bj * 16 + lc);
            ldsm_x4_t(r0, r1, r2, r3, addr);
            b[bj * 2][0] = r0;     b[bj * 2][1] = r1;
            b[bj * 2 + 1][0] = r2; b[bj * 2 + 1][1] = r3;
        }
#pragma unroll
        for (int mi = 0; mi < 4; mi++)
#pragma unroll
            for (int nj = 0; nj < NF; nj++)
                mma_16816(c[mi][nj], a[mi], b[nj]);
    }

    // epilogue: scale by nsrc, convert fp16, store
    const int qr = lane >> 2;
    const int qc = (lane & 3) * 2;
#pragma unroll
    for (int mi = 0; mi < 4; mi++) {
        int r0 = m0 + wm + mi * 16 + qr;
        int r1 = r0 + 8;
        float s0 = 0.f;
        float s1 = 0.f;
        if (r0 < N_NODES) s0 = g_nsrc[r0];
        if (r1 < N_NODES) s1 = g_nsrc[r1];
#pragma unroll
        for (int nj = 0; nj < NF; nj++) {
            int col = wn + nj * 8 + qc;
            if (r0 < N_NODES) {
                __half2 h = __floats2half2_rn(c[mi][nj][0] * s0, c[mi][nj][1] * s0);
                *(uint32_t*)(Y + (size_t)r0 * BN + col) = *(uint32_t*)&h;
            }
            if (r1 < N_NODES) {
                __half2 h = __floats2half2_rn(c[mi][nj][2] * s1, c[mi][nj][3] * s1);
                *(uint32_t*)(Y + (size_t)r1 * BN + col) = *(uint32_t*)&h;
            }
        }
    }
}

// ---------------- aggregation DIM=128: 2 nodes/warp, 16 lanes x uint4 per node ----------------
__global__ __launch_bounds__(256) void agg128x2_kernel(const __half* __restrict__ y,
                                                       __half* __restrict__ out,
                                                       const float* __restrict__ bias) {
    int gw   = (blockIdx.x * blockDim.x + threadIdx.x) >> 5;   // global warp
    int lane = threadIdx.x & 31;
    int node = gw * 2 + (lane >> 4);
    int sub  = lane & 15;                                      // lane within node group
    if (node >= N_NODES) return;

    int c = g_cnt[node]; if (c > CAP) c = CAP;
    const int* lst = g_csr + (size_t)node * CAP;
    const uint4* y4 = (const uint4*)y;                         // 16 uint4 per 128-half row

    float acc[8];
#pragma unroll
    for (int q = 0; q < 8; q++) acc[q] = 0.f;

#pragma unroll 4
    for (int i = 0; i < c; i++) {
        uint4 v = y4[(size_t)lst[i] * 16 + sub];
        float2 f0 = __half22float2(*(const __half2*)&v.x);
        float2 f1 = __half22float2(*(const __half2*)&v.y);
        float2 f2 = __half22float2(*(const __half2*)&v.z);
        float2 f3 = __half22float2(*(const __half2*)&v.w);
        acc[0] += f0.x; acc[1] += f0.y; acc[2] += f1.x; acc[3] += f1.y;
        acc[4] += f2.x; acc[5] += f2.y; acc[6] += f3.x; acc[7] += f3.y;
    }

    float nd = g_ndst[node];
    float4 b0 = ((const float4*)bias)[sub * 2];
    float4 b1 = ((const float4*)bias)[sub * 2 + 1];
    float r0 = fmaxf(fmaf(acc[0], nd, b0.x), 0.f);
    float r1 = fmaxf(fmaf(acc[1], nd, b0.y), 0.f);
    float r2 = fmaxf(fmaf(acc[2], nd, b0.z), 0.f);
    float r3 = fmaxf(fmaf(acc[3], nd, b0.w), 0.f);
    float r4 = fmaxf(fmaf(acc[4], nd, b1.x), 0.f);
    float r5 = fmaxf(fmaf(acc[5], nd, b1.y), 0.f);
    float r6 = fmaxf(fmaf(acc[6], nd, b1.z), 0.f);
    float r7 = fmaxf(fmaf(acc[7], nd, b1.w), 0.f);

    __half2 h0 = __floats2half2_rn(r0, r1);
    __half2 h1 = __floats2half2_rn(r2, r3);
    __half2 h2 = __floats2half2_rn(r4, r5);
    __half2 h3 = __floats2half2_rn(r6, r7);
    uint4 o;
    o.x = *(uint32_t*)&h0; o.y = *(uint32_t*)&h1;
    o.z = *(uint32_t*)&h2; o.w = *(uint32_t*)&h3;
    ((uint4*)out)[(size_t)node * 16 + sub] = o;
}

// ---------------- aggregation DIM=64 + log_softmax: 4 nodes/warp, 8 lanes x uint4 ----------------
__global__ __launch_bounds__(256) void agg64x4_lsm_kernel(const __half* __restrict__ y,
                                                          float* __restrict__ out,
                                                          const float* __restrict__ bias) {
    int gw   = (blockIdx.x * blockDim.x + threadIdx.x) >> 5;
    int lane = threadIdx.x & 31;
    int node = gw * 4 + (lane >> 3);
    int sub  = lane & 7;
    if (node >= N_NODES) return;

    int c = g_cnt[node]; if (c > CAP) c = CAP;
    const int* lst = g_csr + (size_t)node * CAP;
    const uint4* y4 = (const uint4*)y;                         // 8 uint4 per 64-half row

    float acc[8];
#pragma unroll
    for (int q = 0; q < 8; q++) acc[q] = 0.f;

#pragma unroll 4
    for (int i = 0; i < c; i++) {
        uint4 v = y4[(size_t)lst[i] * 8 + sub];
        float2 f0 = __half22float2(*(const __half2*)&v.x);
        float2 f1 = __half22float2(*(const __half2*)&v.y);
        float2 f2 = __half22float2(*(const __half2*)&v.z);
        float2 f3 = __half22float2(*(const __half2*)&v.w);
        acc[0] += f0.x; acc[1] += f0.y; acc[2] += f1.x; acc[3] += f1.y;
        acc[4] += f2.x; acc[5] += f2.y; acc[6] += f3.x; acc[7] += f3.y;
    }

    float nd = g_ndst[node];
    float4 b0 = ((const float4*)bias)[sub * 2];
    float4 b1 = ((const float4*)bias)[sub * 2 + 1];
    float v[8];
    v[0] = fmaxf(fmaf(acc[0], nd, b0.x), 0.f);
    v[1] = fmaxf(fmaf(acc[1], nd, b0.y), 0.f);
    v[2] = fmaxf(fmaf(acc[2], nd, b0.z), 0.f);
    v[3] = fmaxf(fmaf(acc[3], nd, b0.w), 0.f);
    v[4] = fmaxf(fmaf(acc[4], nd, b1.x), 0.f);
    v[5] = fmaxf(fmaf(acc[5], nd, b1.y), 0.f);
    v[6] = fmaxf(fmaf(acc[6], nd, b1.z), 0.f);
    v[7] = fmaxf(fmaf(acc[7], nd, b1.w), 0.f);

    // log_softmax over the 64 values held by this 8-lane group
    float m = v[0];
#pragma unroll
    for (int q = 1; q < 8; q++) m = fmaxf(m, v[q]);
#pragma unroll
    for (int off = 4; off > 0; off >>= 1)
        m = fmaxf(m, __shfl_xor_sync(0xffffffffu, m, off));
    float s = 0.f;
#pragma unroll
    for (int q = 0; q < 8; q++) s += expf(v[q] - m);
#pragma unroll
    for (int off = 4; off > 0; off >>= 1)
        s += __shfl_xor_sync(0xffffffffu, s, off);
    float l = m + logf(s);

    float4 o0 = make_float4(v[0] - l, v[1] - l, v[2] - l, v[3] - l);
    float4 o1 = make_float4(v[4] - l, v[5] - l, v[6] - l, v[7] - l);
    float4* op = (float4*)(out + (size_t)node * 64 + sub * 8);
    op[0] = o0;
    op[1] = o1;
}

// ---------------- launch ----------------
extern "C" void kernel_launch(void* const* d_in, const int* in_sizes, int n_in,
                              void* d_out, int out_size) {
    const float* feats = (const float*)d_in[0];
    const float* W0 = (const float*)d_in[1];
    const float* b0 = (const float*)d_in[2];
    const float* W1 = (const float*)d_in[3];
    const float* b1 = (const float*)d_in[4];
    const float* W2 = (const float*)d_in[5];
    const float* b2 = (const float*)d_in[6];
    const int*  src = (const int*)d_in[7];
    const int*  dst = (const int*)d_in[8];
    float* out = (float*)d_out;

    __half* y16; cudaGetSymbolAddress((void**)&y16, g_y16);
    __half* h16; cudaGetSymbolAddress((void**)&h16, g_h16);
    __half* w0h; cudaGetSymbolAddress((void**)&w0h, g_w0h);
    __half* w1h; cudaGetSymbolAddress((void**)&w1h, g_w1h);
    __half* w2h; cudaGetSymbolAddress((void**)&w2h, g_w2h);

    const int NT = 256;
    int nodeBlocks = (N_NODES + NT - 1) / NT;
    int edgeBlocks = (N_EDGES + NT - 1) / NT;
    int gemmBlocks = (N_NODES + 127) / 128;
    int agg128Blocks = ((N_NODES + 1) / 2 * 32 + NT - 1) / NT;   // 2 nodes/warp
    int agg64Blocks  = ((N_NODES + 3) / 4 * 32 + NT - 1) / NT;   // 4 nodes/warp

    const int SMEM128 = (128 * 136 + 128 * 136) * 2;   // 69632
    const int SMEM64  = (128 * 136 + 128 * 72) * 2;    // 53248
    cudaFuncSetAttribute(hgemm_kernel<128, true>,  cudaFuncAttributeMaxDynamicSharedMemorySize, SMEM128);
    cudaFuncSetAttribute(hgemm_kernel<128, false>, cudaFuncAttributeMaxDynamicSharedMemorySize, SMEM128);
    cudaFuncSetAttribute(hgemm_kernel<64, false>,  cudaFuncAttributeMaxDynamicSharedMemorySize, SMEM64);

    zero_kernel<<<nodeBlocks, NT>>>();
    build_kernel<<<edgeBlocks, NT>>>(src, dst);
    norm_kernel<<<nodeBlocks, NT>>>();
    cvtw_kernel<<<40, NT>>>(W0, W1, W2, w0h, w1h, w2h);

    hgemm_kernel<128, true><<<gemmBlocks, NT, SMEM128>>>(feats, (const __half*)0, w0h, y16);
    agg128x2_kernel<<<agg128Blocks, NT>>>(y16, h16, b0);

    hgemm_kernel<128, false><<<gemmBlocks, NT, SMEM128>>>((const float*)0, h16, w1h, y16);
    agg128x2_kernel<<<agg128Blocks, NT>>>(y16, h16, b1);

    hgemm_kernel<64, false><<<gemmBlocks, NT, SMEM64>>>((const float*)0, h16, w2h, y16);
    agg64x4_lsm_kernel<<<agg64Blocks, NT>>>(y16, out, b2);
}